// round 2
// baseline (speedup 1.0000x reference)
#include <cuda_runtime.h>
#include <cuda_bf16.h>
#include <cstdint>

#define B_SZ 512
#define H_SZ 1024
#define L_SZ 64
#define V_SZ 50257
#define LDL  50304   // padded logits row stride (128*393)

// ---------------- scratch (device globals; no allocation allowed) ----------
__device__ float g_xin[B_SZ * 2 * H_SZ];          // concat(emb, attn_applied)  4MB
__device__ float g_x[B_SZ * H_SZ];                // combine output             2MB
__device__ float g_gi[B_SZ * 3 * H_SZ];           // x @ W_ih^T                 6MB
__device__ float g_gh[B_SZ * 3 * H_SZ];           // h0 @ W_hh^T                6MB
__device__ float g_h1[B_SZ * H_SZ];               // GRU output                 2MB
__device__ float g_logits[(size_t)B_SZ * LDL];    // pre-softmax logits       103MB

// ===========================================================================
// K1: attention (scores -> softmax -> attn_applied) + build concat input
//     One block handles 4 batch rows. 128 blocks x 256 threads.
// ===========================================================================
__global__ void __launch_bounds__(256) attn_kernel(
    const float* __restrict__ emb, const float* __restrict__ h0,
    const float* __restrict__ enc, const float* __restrict__ attn_W,
    const float* __restrict__ attn_b, float* __restrict__ aw_out)
{
    __shared__ float sE[4][H_SZ];
    __shared__ float sH[4][H_SZ];
    __shared__ float sS[4][L_SZ];
    __shared__ float sP[4][4][L_SZ];

    int tid = threadIdx.x;
    int r0  = blockIdx.x * 4;

    for (int i = tid; i < 4 * H_SZ; i += 256) {
        int r = i >> 10, c = i & 1023;
        sE[r][c] = emb[(size_t)(r0 + r) * H_SZ + c];
        sH[r][c] = h0 [(size_t)(r0 + r) * H_SZ + c];
    }
    __syncthreads();

    // scores = concat(emb, h0) @ attn_W   (2048 x 64), split k over 4 groups
    {
        int l = tid & 63, gq = tid >> 6;
        float acc[4] = {0.f, 0.f, 0.f, 0.f};
        int kbeg = gq * 512, kend = kbeg + 512;
        for (int k = kbeg; k < kend; k++) {
            float w = attn_W[(size_t)k * L_SZ + l];
            if (k < H_SZ) {
                #pragma unroll
                for (int r = 0; r < 4; r++) acc[r] += sE[r][k] * w;
            } else {
                #pragma unroll
                for (int r = 0; r < 4; r++) acc[r] += sH[r][k - H_SZ] * w;
            }
        }
        #pragma unroll
        for (int r = 0; r < 4; r++) sP[gq][r][l] = acc[r];
    }
    __syncthreads();
    {
        int r = tid >> 6, l = tid & 63;
        sS[r][l] = sP[0][r][l] + sP[1][r][l] + sP[2][r][l] + sP[3][r][l] + attn_b[l];
    }
    __syncthreads();

    // softmax over L=64, one warp per row (warps 0..3)
    int warp = tid >> 5, lane = tid & 31;
    if (warp < 4) {
        int r = warp;
        float v0 = sS[r][lane], v1 = sS[r][lane + 32];
        float m = fmaxf(v0, v1);
        #pragma unroll
        for (int o = 16; o; o >>= 1) m = fmaxf(m, __shfl_xor_sync(0xffffffffu, m, o));
        float e0 = expf(v0 - m), e1 = expf(v1 - m);
        float s = e0 + e1;
        #pragma unroll
        for (int o = 16; o; o >>= 1) s += __shfl_xor_sync(0xffffffffu, s, o);
        float inv = 1.0f / s;
        float w0 = e0 * inv, w1 = e1 * inv;
        sS[r][lane] = w0; sS[r][lane + 32] = w1;
        if (aw_out) {
            aw_out[(size_t)(r0 + r) * L_SZ + lane]      = w0;
            aw_out[(size_t)(r0 + r) * L_SZ + lane + 32] = w1;
        }
    }
    __syncthreads();

    // attn_applied = weights @ enc ; write concat(emb, attn_applied) to g_xin
    for (int cc = 0; cc < 4; cc++) {
        int h = cc * 256 + tid;
        float a[4] = {0.f, 0.f, 0.f, 0.f};
        for (int l = 0; l < L_SZ; l++) {
            float e = enc[(size_t)l * H_SZ + h];
            #pragma unroll
            for (int r = 0; r < 4; r++) a[r] += sS[r][l] * e;
        }
        #pragma unroll
        for (int r = 0; r < 4; r++) {
            g_xin[(size_t)(r0 + r) * (2 * H_SZ) + h]        = sE[r][h];
            g_xin[(size_t)(r0 + r) * (2 * H_SZ) + H_SZ + h] = a[r];
        }
    }
}

// ===========================================================================
// K2/K3: tf32 mma GEMM core.  C(MxN) = A(MxK) @ B + bias (+relu)
//   b_kmajor=1 : B stored (N,K) k-contiguous  (i.e. op is A @ B^T, PyTorch W)
//   b_kmajor=0 : B stored (K,N) n-contiguous
//   Block tile 64x64x32, 8 warps (2m x 4n), warp tile 32x16, m16n8k8 tf32.
//   Called from thin __global__ wrappers that bind the scratch globals, so
//   the host launcher never needs cudaGetSymbolAddress.
// ===========================================================================
__device__ __forceinline__ void gemm_tf32_core(
    const float* __restrict__ A, const float* __restrict__ Bm,
    const float* __restrict__ bias, float* __restrict__ C,
    int N, int K, int b_kmajor, int relu)
{
    __shared__ float sA[64][36];
    __shared__ float sB[64][36];   // stored (n, k)

    int tid = threadIdx.x;
    int warp = tid >> 5, lane = tid & 31, g = lane >> 2, q = lane & 3;
    int wm = warp & 1, wn = warp >> 1;
    int bm0 = blockIdx.x * 64, bn0 = blockIdx.y * 64;

    float acc[2][2][4];
    #pragma unroll
    for (int i = 0; i < 2; i++)
        #pragma unroll
        for (int j = 0; j < 2; j++)
            #pragma unroll
            for (int t = 0; t < 4; t++) acc[i][j][t] = 0.f;

    for (int k0 = 0; k0 < K; k0 += 32) {
        __syncthreads();
        #pragma unroll
        for (int s = 0; s < 2; s++) {
            int ii = tid + s * 256;
            int r = ii >> 3, c4 = (ii & 7) * 4;
            float4 v = *(const float4*)(A + (size_t)(bm0 + r) * K + k0 + c4);
            sA[r][c4] = v.x; sA[r][c4 + 1] = v.y; sA[r][c4 + 2] = v.z; sA[r][c4 + 3] = v.w;
        }
        if (b_kmajor) {
            #pragma unroll
            for (int s = 0; s < 2; s++) {
                int ii = tid + s * 256;
                int r = ii >> 3, c4 = (ii & 7) * 4;
                float4 v = *(const float4*)(Bm + (size_t)(bn0 + r) * K + k0 + c4);
                sB[r][c4] = v.x; sB[r][c4 + 1] = v.y; sB[r][c4 + 2] = v.z; sB[r][c4 + 3] = v.w;
            }
        } else {
            #pragma unroll
            for (int s = 0; s < 2; s++) {
                int ii = tid + s * 256;
                int kr = ii >> 4, c4 = (ii & 15) * 4;
                float4 v = *(const float4*)(Bm + (size_t)(k0 + kr) * N + bn0 + c4);
                sB[c4][kr] = v.x; sB[c4 + 1][kr] = v.y; sB[c4 + 2][kr] = v.z; sB[c4 + 3][kr] = v.w;
            }
        }
        __syncthreads();

        #pragma unroll
        for (int kk = 0; kk < 4; kk++) {
            int ko = kk * 8;
            unsigned a[2][4], b[2][2];
            #pragma unroll
            for (int mt = 0; mt < 2; mt++) {
                int rm = wm * 32 + mt * 16;
                a[mt][0] = __float_as_uint(sA[rm + g][ko + q]);
                a[mt][1] = __float_as_uint(sA[rm + g + 8][ko + q]);
                a[mt][2] = __float_as_uint(sA[rm + g][ko + q + 4]);
                a[mt][3] = __float_as_uint(sA[rm + g + 8][ko + q + 4]);
            }
            #pragma unroll
            for (int nt = 0; nt < 2; nt++) {
                int cn = wn * 16 + nt * 8 + g;
                b[nt][0] = __float_as_uint(sB[cn][ko + q]);
                b[nt][1] = __float_as_uint(sB[cn][ko + q + 4]);
            }
            #pragma unroll
            for (int mt = 0; mt < 2; mt++)
                #pragma unroll
                for (int nt = 0; nt < 2; nt++)
                    asm volatile(
                        "mma.sync.aligned.m16n8k8.row.col.f32.tf32.tf32.f32 "
                        "{%0,%1,%2,%3}, {%4,%5,%6,%7}, {%8,%9}, {%0,%1,%2,%3};"
                        : "+f"(acc[mt][nt][0]), "+f"(acc[mt][nt][1]),
                          "+f"(acc[mt][nt][2]), "+f"(acc[mt][nt][3])
                        : "r"(a[mt][0]), "r"(a[mt][1]), "r"(a[mt][2]), "r"(a[mt][3]),
                          "r"(b[nt][0]), "r"(b[nt][1]));
        }
    }

    #pragma unroll
    for (int mt = 0; mt < 2; mt++) {
        int row = bm0 + wm * 32 + mt * 16 + g;
        #pragma unroll
        for (int nt = 0; nt < 2; nt++) {
            int col = bn0 + wn * 16 + nt * 8 + 2 * q;
            float b0 = bias[col], b1 = bias[col + 1];
            float v0 = acc[mt][nt][0] + b0, v1 = acc[mt][nt][1] + b1;
            float v2 = acc[mt][nt][2] + b0, v3 = acc[mt][nt][3] + b1;
            if (relu) {
                v0 = fmaxf(v0, 0.f); v1 = fmaxf(v1, 0.f);
                v2 = fmaxf(v2, 0.f); v3 = fmaxf(v3, 0.f);
            }
            C[(size_t)row * N + col] = v0;       C[(size_t)row * N + col + 1] = v1;
            C[(size_t)(row + 8) * N + col] = v2; C[(size_t)(row + 8) * N + col + 1] = v3;
        }
    }
}

// thin wrappers binding device-global scratch
__global__ void __launch_bounds__(256) gemm_comb_kernel(
    const float* __restrict__ comb_W, const float* __restrict__ comb_b)
{
    gemm_tf32_core(g_xin, comb_W, comb_b, g_x, H_SZ, 2 * H_SZ, /*kmajor=*/0, /*relu=*/1);
}
__global__ void __launch_bounds__(256) gemm_gih_kernel(
    const float* __restrict__ W_ih, const float* __restrict__ b_ih)
{
    gemm_tf32_core(g_x, W_ih, b_ih, g_gi, 3 * H_SZ, H_SZ, 1, 0);
}
__global__ void __launch_bounds__(256) gemm_ghh_kernel(
    const float* __restrict__ h0, const float* __restrict__ W_hh,
    const float* __restrict__ b_hh)
{
    gemm_tf32_core(h0, W_hh, b_hh, g_gh, 3 * H_SZ, H_SZ, 1, 0);
}

// ===========================================================================
// K4: GRU elementwise (PyTorch gate order r, z, n)
// ===========================================================================
__global__ void __launch_bounds__(256) gru_kernel(
    const float* __restrict__ h0, float* __restrict__ h1_extra)
{
    int idx = blockIdx.x * 256 + threadIdx.x;
    if (idx >= B_SZ * H_SZ) return;
    int row = idx >> 10, j = idx & 1023;
    const float* gi = g_gi + (size_t)row * 3 * H_SZ;
    const float* gh = g_gh + (size_t)row * 3 * H_SZ;
    float rg = 1.f / (1.f + expf(-(gi[j] + gh[j])));
    float zg = 1.f / (1.f + expf(-(gi[H_SZ + j] + gh[H_SZ + j])));
    float ng = tanhf(gi[2 * H_SZ + j] + rg * gh[2 * H_SZ + j]);
    float h0v = h0[idx];
    float h1 = (1.f - zg) * ng + zg * h0v;
    g_h1[idx] = h1;
    if (h1_extra) h1_extra[idx] = h1;
}

// ===========================================================================
// K5: bf16 mma GEMM for logits = h1(512x1024) @ out_W(1024xV) + out_b.
//   out_W converted fp32->bf16 on the fly in the smem loader (transposed to
//   (n,k)).  Block tile 128x128x32, 8 warps (2m x 4n), warp tile 64x32,
//   m16n8k16 bf16, reg-prefetch double-buffered smem.
// ===========================================================================
__global__ void __launch_bounds__(256) gemm_out_kernel(
    const float* __restrict__ W, const float* __restrict__ bias)
{
    __shared__ __nv_bfloat16 sA[2][128][40];   // (m, k)
    __shared__ __nv_bfloat16 sB[2][128][40];   // (n, k)
    const int K = 1024;
    const float* __restrict__ A = g_h1;
    float* __restrict__ Clog = g_logits;

    int tid = threadIdx.x;
    int warp = tid >> 5, lane = tid & 31, g = lane >> 2, q = lane & 3;
    int wm = warp & 1, wn = warp >> 1;
    int bm0 = blockIdx.x * 128, bn0 = blockIdx.y * 128;

    float acc[4][4][4];
    #pragma unroll
    for (int i = 0; i < 4; i++)
        #pragma unroll
        for (int j = 0; j < 4; j++)
            #pragma unroll
            for (int t = 0; t < 4; t++) acc[i][j][t] = 0.f;

    float pa[16], pb[16];

    // prologue: stage 0
    #pragma unroll
    for (int s = 0; s < 16; s++) {
        int ii = tid + s * 256;
        int ar = ii >> 5, ac = ii & 31;
        pa[s] = A[(size_t)(bm0 + ar) * K + ac];
        int kr = ii >> 7, nn = ii & 127;
        int n = bn0 + nn;
        pb[s] = (n < V_SZ) ? W[(size_t)kr * V_SZ + n] : 0.0f;
    }
    #pragma unroll
    for (int s = 0; s < 16; s++) {
        int ii = tid + s * 256;
        int ar = ii >> 5, ac = ii & 31;
        sA[0][ar][ac] = __float2bfloat16(pa[s]);
        int kr = ii >> 7, nn = ii & 127;
        sB[0][nn][kr] = __float2bfloat16(pb[s]);
    }
    __syncthreads();

    const int NS = K / 32;   // 32 stages
    for (int ks = 0; ks < NS; ks++) {
        int nxt = ks + 1;
        if (nxt < NS) {
            int k0 = nxt * 32;
            #pragma unroll
            for (int s = 0; s < 16; s++) {
                int ii = tid + s * 256;
                int ar = ii >> 5, ac = ii & 31;
                pa[s] = A[(size_t)(bm0 + ar) * K + k0 + ac];
                int kr = ii >> 7, nn = ii & 127;
                int n = bn0 + nn;
                pb[s] = (n < V_SZ) ? W[(size_t)(k0 + kr) * V_SZ + n] : 0.0f;
            }
        }
        int buf = ks & 1;
        #pragma unroll
        for (int kk = 0; kk < 2; kk++) {
            int koff = kk * 16;
            unsigned a[4][4], b[4][2];
            #pragma unroll
            for (int mt = 0; mt < 4; mt++) {
                int rm = wm * 64 + mt * 16;
                a[mt][0] = *(const unsigned*)&sA[buf][rm + g][koff + 2 * q];
                a[mt][1] = *(const unsigned*)&sA[buf][rm + g + 8][koff + 2 * q];
                a[mt][2] = *(const unsigned*)&sA[buf][rm + g][koff + 2 * q + 8];
                a[mt][3] = *(const unsigned*)&sA[buf][rm + g + 8][koff + 2 * q + 8];
            }
            #pragma unroll
            for (int nt = 0; nt < 4; nt++) {
                int cn = wn * 32 + nt * 8 + g;
                b[nt][0] = *(const unsigned*)&sB[buf][cn][koff + 2 * q];
                b[nt][1] = *(const unsigned*)&sB[buf][cn][koff + 2 * q + 8];
            }
            #pragma unroll
            for (int mt = 0; mt < 4; mt++)
                #pragma unroll
                for (int nt = 0; nt < 4; nt++)
                    asm volatile(
                        "mma.sync.aligned.m16n8k16.row.col.f32.bf16.bf16.f32 "
                        "{%0,%1,%2,%3}, {%4,%5,%6,%7}, {%8,%9}, {%0,%1,%2,%3};"
                        : "+f"(acc[mt][nt][0]), "+f"(acc[mt][nt][1]),
                          "+f"(acc[mt][nt][2]), "+f"(acc[mt][nt][3])
                        : "r"(a[mt][0]), "r"(a[mt][1]), "r"(a[mt][2]), "r"(a[mt][3]),
                          "r"(b[nt][0]), "r"(b[nt][1]));
        }
        if (nxt < NS) {
            int ob = nxt & 1;
            #pragma unroll
            for (int s = 0; s < 16; s++) {
                int ii = tid + s * 256;
                int ar = ii >> 5, ac = ii & 31;
                sA[ob][ar][ac] = __float2bfloat16(pa[s]);
                int kr = ii >> 7, nn = ii & 127;
                sB[ob][nn][kr] = __float2bfloat16(pb[s]);
            }
        }
        __syncthreads();
    }

    #pragma unroll
    for (int mt = 0; mt < 4; mt++) {
        int row = bm0 + wm * 64 + mt * 16 + g;
        #pragma unroll
        for (int nt = 0; nt < 4; nt++) {
            int col = bn0 + wn * 32 + nt * 8 + 2 * q;
            float* p0 = Clog + (size_t)row * LDL + col;
            float* p1 = Clog + (size_t)(row + 8) * LDL + col;
            if (col < V_SZ) {
                float bv = bias[col];
                p0[0] = acc[mt][nt][0] + bv;
                p1[0] = acc[mt][nt][2] + bv;
            }
            if (col + 1 < V_SZ) {
                float bv = bias[col + 1];
                p0[1] = acc[mt][nt][1] + bv;
                p1[1] = acc[mt][nt][3] + bv;
            }
        }
    }
}

// ===========================================================================
// K6: row-wise log_softmax, no big smem: pass 1 online (max,sum), pass 2 write.
//     One block of 256 threads per row.
// ===========================================================================
__global__ void __launch_bounds__(256) lsm_kernel(float* __restrict__ outp)
{
    __shared__ float sredm[8];
    __shared__ float sreds[8];
    int row = blockIdx.x, tid = threadIdx.x, lane = tid & 31, warp = tid >> 5;
    const float* lg = g_logits + (size_t)row * LDL;

    // pass 1: online max & sum (vectorized float4; LDL mult of 4, tail guarded)
    float m = -3.4e38f, s = 0.f;
    for (int v4 = tid * 4; v4 < V_SZ; v4 += 256 * 4) {
        float4 x = *(const float4*)(lg + v4);
        if (v4 + 3 >= V_SZ) {           // tail: only lanes < V valid
            float xs[4] = {x.x, x.y, x.z, x.w};
            for (int t = 0; t < 4; t++) {
                if (v4 + t < V_SZ) {
                    float xv = xs[t];
                    float mn = fmaxf(m, xv);
                    s = s * expf(m - mn) + expf(xv - mn);
                    m = mn;
                }
            }
        } else {
            float lm = fmaxf(fmaxf(x.x, x.y), fmaxf(x.z, x.w));
            float mn = fmaxf(m, lm);
            s = s * expf(m - mn)
              + expf(x.x - mn) + expf(x.y - mn) + expf(x.z - mn) + expf(x.w - mn);
            m = mn;
        }
    }
    // warp merge
    #pragma unroll
    for (int o = 16; o; o >>= 1) {
        float mo = __shfl_xor_sync(0xffffffffu, m, o);
        float so = __shfl_xor_sync(0xffffffffu, s, o);
        float mn = fmaxf(m, mo);
        s = s * expf(m - mn) + so * expf(mo - mn);
        m = mn;
    }
    if (lane == 0) { sredm[warp] = m; sreds[warp] = s; }
    __syncthreads();
    float mall = sredm[0];
    #pragma unroll
    for (int i = 1; i < 8; i++) mall = fmaxf(mall, sredm[i]);
    float tot = 0.f;
    #pragma unroll
    for (int i = 0; i < 8; i++) tot += sreds[i] * expf(sredm[i] - mall);

    float lse = mall + logf(tot);

    // pass 2: write out (logits row is hot in L2)
    float* op = outp + (size_t)row * V_SZ;
    for (int v = tid; v < V_SZ; v += 256) op[v] = lg[v] - lse;
}

// ===========================================================================
// host launcher — kernel launches only, no other CUDA APIs
// ===========================================================================
extern "C" void kernel_launch(void* const* d_in, const int* in_sizes, int n_in,
                              void* d_out, int out_size)
{
    const float* input_emb = (const float*)d_in[0];   // (1,B,H)
    const float* hidden    = (const float*)d_in[1];   // (1,B,H)
    const float* enc       = (const float*)d_in[2];   // (L,H)
    const float* attn_W    = (const float*)d_in[3];   // (2H,L)
    const float* attn_b    = (const float*)d_in[4];   // (L)
    const float* comb_W    = (const float*)d_in[5];   // (2H,H)
    const float* comb_b    = (const float*)d_in[6];   // (H)
    const float* W_ih      = (const float*)d_in[7];   // (3H,H)
    const float* W_hh      = (const float*)d_in[8];   // (3H,H)
    const float* b_ih      = (const float*)d_in[9];   // (3H)
    const float* b_hh      = (const float*)d_in[10];  // (3H)
    const float* out_W     = (const float*)d_in[11];  // (H,V)
    const float* out_b     = (const float*)d_in[12];  // (V)

    float* outp = (float*)d_out;
    long long osz = (long long)out_size;
    const long long OV = (long long)B_SZ * V_SZ;
    float* h1_out = (osz >= OV + (long long)B_SZ * H_SZ)
                        ? outp + (size_t)OV : nullptr;
    float* aw_out = (osz >= OV + (long long)B_SZ * H_SZ + (long long)B_SZ * L_SZ)
                        ? outp + (size_t)OV + (size_t)B_SZ * H_SZ : nullptr;

    // K1: attention + concat -> g_xin
    attn_kernel<<<B_SZ / 4, 256>>>(input_emb, hidden, enc, attn_W, attn_b, aw_out);

    // K2: g_x = relu(g_xin @ comb_W + comb_b)
    {
        dim3 grid(B_SZ / 64, H_SZ / 64);
        gemm_comb_kernel<<<grid, 256>>>(comb_W, comb_b);
    }
    // K3a/b: g_gi = g_x @ W_ih^T + b_ih ; g_gh = h0 @ W_hh^T + b_hh
    {
        dim3 grid(B_SZ / 64, 3 * H_SZ / 64);
        gemm_gih_kernel<<<grid, 256>>>(W_ih, b_ih);
        gemm_ghh_kernel<<<grid, 256>>>(hidden, W_hh, b_hh);
    }
    // K4: GRU elementwise -> g_h1 (+ h1 slice of output)
    gru_kernel<<<(B_SZ * H_SZ) / 256, 256>>>(hidden, h1_out);

    // K5: g_logits = g_h1 @ out_W + out_b (bf16 mma)
    {
        dim3 grid(B_SZ / 128, (V_SZ + 127) / 128);   // m-tile fastest -> L2 reuse of W
        gemm_out_kernel<<<grid, 256>>>(out_W, out_b);
    }
    // K6: log_softmax -> final output
    lsm_kernel<<<B_SZ, 256>>>(outp);
}

// round 3
// speedup vs baseline: 1.0783x; 1.0783x over previous
#include <cuda_runtime.h>
#include <cuda_bf16.h>
#include <cstdint>

#define B_SZ 512
#define H_SZ 1024
#define L_SZ 64
#define V_SZ 50257
#define LDL  50304   // padded logits row stride
#define NB_T 393     // number of 128-wide n-tiles in vocab GEMM

// ---------------- scratch (device globals; no allocation allowed) ----------
__device__ float g_xin[B_SZ * 2 * H_SZ];
__device__ float g_x[B_SZ * H_SZ];
__device__ float g_gi[B_SZ * 3 * H_SZ];
__device__ float g_gh[B_SZ * 3 * H_SZ];
__device__ __nv_bfloat16 g_h1b[B_SZ * H_SZ];
__device__ float g_logits[(size_t)B_SZ * LDL];
__device__ float2 g_part[B_SZ * 400];           // per (row, n-tile) (max, sumexp)

// ===========================================================================
// K1: attention (scores -> softmax -> attn_applied) + build concat input
// ===========================================================================
__global__ void __launch_bounds__(256) attn_kernel(
    const float* __restrict__ emb, const float* __restrict__ h0,
    const float* __restrict__ enc, const float* __restrict__ attn_W,
    const float* __restrict__ attn_b, float* __restrict__ aw_out)
{
    __shared__ float sE[4][H_SZ];
    __shared__ float sH[4][H_SZ];
    __shared__ float sS[4][L_SZ];
    __shared__ float sP[4][4][L_SZ];

    int tid = threadIdx.x;
    int r0  = blockIdx.x * 4;

    for (int i = tid; i < 4 * H_SZ; i += 256) {
        int r = i >> 10, c = i & 1023;
        sE[r][c] = emb[(size_t)(r0 + r) * H_SZ + c];
        sH[r][c] = h0 [(size_t)(r0 + r) * H_SZ + c];
    }
    __syncthreads();

    {
        int l = tid & 63, gq = tid >> 6;
        float acc[4] = {0.f, 0.f, 0.f, 0.f};
        int kbeg = gq * 512, kend = kbeg + 512;
        for (int k = kbeg; k < kend; k++) {
            float w = attn_W[(size_t)k * L_SZ + l];
            if (k < H_SZ) {
                #pragma unroll
                for (int r = 0; r < 4; r++) acc[r] += sE[r][k] * w;
            } else {
                #pragma unroll
                for (int r = 0; r < 4; r++) acc[r] += sH[r][k - H_SZ] * w;
            }
        }
        #pragma unroll
        for (int r = 0; r < 4; r++) sP[gq][r][l] = acc[r];
    }
    __syncthreads();
    {
        int r = tid >> 6, l = tid & 63;
        sS[r][l] = sP[0][r][l] + sP[1][r][l] + sP[2][r][l] + sP[3][r][l] + attn_b[l];
    }
    __syncthreads();

    int warp = tid >> 5, lane = tid & 31;
    if (warp < 4) {
        int r = warp;
        float v0 = sS[r][lane], v1 = sS[r][lane + 32];
        float m = fmaxf(v0, v1);
        #pragma unroll
        for (int o = 16; o; o >>= 1) m = fmaxf(m, __shfl_xor_sync(0xffffffffu, m, o));
        float e0 = expf(v0 - m), e1 = expf(v1 - m);
        float s = e0 + e1;
        #pragma unroll
        for (int o = 16; o; o >>= 1) s += __shfl_xor_sync(0xffffffffu, s, o);
        float inv = 1.0f / s;
        float w0 = e0 * inv, w1 = e1 * inv;
        sS[r][lane] = w0; sS[r][lane + 32] = w1;
        if (aw_out) {
            aw_out[(size_t)(r0 + r) * L_SZ + lane]      = w0;
            aw_out[(size_t)(r0 + r) * L_SZ + lane + 32] = w1;
        }
    }
    __syncthreads();

    for (int cc = 0; cc < 4; cc++) {
        int h = cc * 256 + tid;
        float a[4] = {0.f, 0.f, 0.f, 0.f};
        for (int l = 0; l < L_SZ; l++) {
            float e = enc[(size_t)l * H_SZ + h];
            #pragma unroll
            for (int r = 0; r < 4; r++) a[r] += sS[r][l] * e;
        }
        #pragma unroll
        for (int r = 0; r < 4; r++) {
            g_xin[(size_t)(r0 + r) * (2 * H_SZ) + h]        = sE[r][h];
            g_xin[(size_t)(r0 + r) * (2 * H_SZ) + H_SZ + h] = a[r];
        }
    }
}

// ===========================================================================
// tf32 mma GEMM core (shared arrays passed in so wrappers can fuse paths)
// ===========================================================================
__device__ __forceinline__ void gemm_tf32_core(
    float (*sA)[36], float (*sB)[36],
    const float* __restrict__ A, const float* __restrict__ Bm,
    const float* __restrict__ bias, float* __restrict__ C,
    int N, int K, int b_kmajor, int relu, int bm0, int bn0)
{
    int tid = threadIdx.x;
    int warp = tid >> 5, lane = tid & 31, g = lane >> 2, q = lane & 3;
    int wm = warp & 1, wn = warp >> 1;

    float acc[2][2][4];
    #pragma unroll
    for (int i = 0; i < 2; i++)
        #pragma unroll
        for (int j = 0; j < 2; j++)
            #pragma unroll
            for (int t = 0; t < 4; t++) acc[i][j][t] = 0.f;

    for (int k0 = 0; k0 < K; k0 += 32) {
        __syncthreads();
        #pragma unroll
        for (int s = 0; s < 2; s++) {
            int ii = tid + s * 256;
            int r = ii >> 3, c4 = (ii & 7) * 4;
            float4 v = *(const float4*)(A + (size_t)(bm0 + r) * K + k0 + c4);
            sA[r][c4] = v.x; sA[r][c4 + 1] = v.y; sA[r][c4 + 2] = v.z; sA[r][c4 + 3] = v.w;
        }
        if (b_kmajor) {
            #pragma unroll
            for (int s = 0; s < 2; s++) {
                int ii = tid + s * 256;
                int r = ii >> 3, c4 = (ii & 7) * 4;
                float4 v = *(const float4*)(Bm + (size_t)(bn0 + r) * K + k0 + c4);
                sB[r][c4] = v.x; sB[r][c4 + 1] = v.y; sB[r][c4 + 2] = v.z; sB[r][c4 + 3] = v.w;
            }
        } else {
            #pragma unroll
            for (int s = 0; s < 2; s++) {
                int ii = tid + s * 256;
                int kr = ii >> 4, c4 = (ii & 15) * 4;
                float4 v = *(const float4*)(Bm + (size_t)(k0 + kr) * N + bn0 + c4);
                sB[c4][kr] = v.x; sB[c4 + 1][kr] = v.y; sB[c4 + 2][kr] = v.z; sB[c4 + 3][kr] = v.w;
            }
        }
        __syncthreads();

        #pragma unroll
        for (int kk = 0; kk < 4; kk++) {
            int ko = kk * 8;
            unsigned a[2][4], b[2][2];
            #pragma unroll
            for (int mt = 0; mt < 2; mt++) {
                int rm = wm * 32 + mt * 16;
                a[mt][0] = __float_as_uint(sA[rm + g][ko + q]);
                a[mt][1] = __float_as_uint(sA[rm + g + 8][ko + q]);
                a[mt][2] = __float_as_uint(sA[rm + g][ko + q + 4]);
                a[mt][3] = __float_as_uint(sA[rm + g + 8][ko + q + 4]);
            }
            #pragma unroll
            for (int nt = 0; nt < 2; nt++) {
                int cn = wn * 16 + nt * 8 + g;
                b[nt][0] = __float_as_uint(sB[cn][ko + q]);
                b[nt][1] = __float_as_uint(sB[cn][ko + q + 4]);
            }
            #pragma unroll
            for (int mt = 0; mt < 2; mt++)
                #pragma unroll
                for (int nt = 0; nt < 2; nt++)
                    asm volatile(
                        "mma.sync.aligned.m16n8k8.row.col.f32.tf32.tf32.f32 "
                        "{%0,%1,%2,%3}, {%4,%5,%6,%7}, {%8,%9}, {%0,%1,%2,%3};"
                        : "+f"(acc[mt][nt][0]), "+f"(acc[mt][nt][1]),
                          "+f"(acc[mt][nt][2]), "+f"(acc[mt][nt][3])
                        : "r"(a[mt][0]), "r"(a[mt][1]), "r"(a[mt][2]), "r"(a[mt][3]),
                          "r"(b[nt][0]), "r"(b[nt][1]));
        }
    }

    #pragma unroll
    for (int mt = 0; mt < 2; mt++) {
        int row = bm0 + wm * 32 + mt * 16 + g;
        #pragma unroll
        for (int nt = 0; nt < 2; nt++) {
            int col = bn0 + wn * 16 + nt * 8 + 2 * q;
            float b0 = bias[col], b1 = bias[col + 1];
            float v0 = acc[mt][nt][0] + b0, v1 = acc[mt][nt][1] + b1;
            float v2 = acc[mt][nt][2] + b0, v3 = acc[mt][nt][3] + b1;
            if (relu) {
                v0 = fmaxf(v0, 0.f); v1 = fmaxf(v1, 0.f);
                v2 = fmaxf(v2, 0.f); v3 = fmaxf(v3, 0.f);
            }
            C[(size_t)row * N + col] = v0;       C[(size_t)row * N + col + 1] = v1;
            C[(size_t)(row + 8) * N + col] = v2; C[(size_t)(row + 8) * N + col + 1] = v3;
        }
    }
}

// fused comb (z==0) + ghh (z==1..3): independent GEMMs, one launch
__global__ void __launch_bounds__(256) gemm_comb_ghh_kernel(
    const float* __restrict__ comb_W, const float* __restrict__ comb_b,
    const float* __restrict__ h0, const float* __restrict__ W_hh,
    const float* __restrict__ b_hh)
{
    __shared__ float sA[64][36];
    __shared__ float sB[64][36];
    if (blockIdx.z == 0) {
        gemm_tf32_core(sA, sB, g_xin, comb_W, comb_b, g_x,
                       H_SZ, 2 * H_SZ, 0, 1, blockIdx.x * 64, blockIdx.y * 64);
    } else {
        int bn = (blockIdx.z - 1) * 16 + blockIdx.y;
        gemm_tf32_core(sA, sB, h0, W_hh, b_hh, g_gh,
                       3 * H_SZ, H_SZ, 1, 0, blockIdx.x * 64, bn * 64);
    }
}
__global__ void __launch_bounds__(256) gemm_gih_kernel(
    const float* __restrict__ W_ih, const float* __restrict__ b_ih)
{
    __shared__ float sA[64][36];
    __shared__ float sB[64][36];
    gemm_tf32_core(sA, sB, g_x, W_ih, b_ih, g_gi,
                   3 * H_SZ, H_SZ, 1, 0, blockIdx.x * 64, blockIdx.y * 64);
}

// ===========================================================================
// K4: GRU elementwise; writes fp32 h1 to output slice + bf16 h1 for vocab GEMM
// ===========================================================================
__global__ void __launch_bounds__(256) gru_kernel(
    const float* __restrict__ h0, float* __restrict__ h1_extra)
{
    int idx = blockIdx.x * 256 + threadIdx.x;
    if (idx >= B_SZ * H_SZ) return;
    int row = idx >> 10, j = idx & 1023;
    const float* gi = g_gi + (size_t)row * 3 * H_SZ;
    const float* gh = g_gh + (size_t)row * 3 * H_SZ;
    float rg = 1.f / (1.f + expf(-(gi[j] + gh[j])));
    float zg = 1.f / (1.f + expf(-(gi[H_SZ + j] + gh[H_SZ + j])));
    float ng = tanhf(gi[2 * H_SZ + j] + rg * gh[2 * H_SZ + j]);
    float h0v = h0[idx];
    float h1 = (1.f - zg) * ng + zg * h0v;
    g_h1b[idx] = __float2bfloat16(h1);
    if (h1_extra) h1_extra[idx] = h1;
}

// ===========================================================================
// K5: bf16 mma vocab GEMM, ldmatrix + swizzled smem + packed STS.128.
//   Tile 128m x 128n x 32k double-buffered, 8 warps (2m x 4n), m16n8k16.
//   A smem (m,k): 64B rows, chunk swizzle c ^ ((r>>1)&3)
//   B smem (k,n): 256B rows, chunk swizzle c ^ (k&7)
//   Epilogue: bias + logits store + per-(row, n-tile) (max, sumexp) partials.
// ===========================================================================
#define LDMX4(R0,R1,R2,R3,ADDR) \
    asm volatile("ldmatrix.sync.aligned.m8n8.x4.shared.b16 {%0,%1,%2,%3}, [%4];" \
        : "=r"(R0), "=r"(R1), "=r"(R2), "=r"(R3) : "r"(ADDR))
#define LDMX4T(R0,R1,R2,R3,ADDR) \
    asm volatile("ldmatrix.sync.aligned.m8n8.x4.trans.shared.b16 {%0,%1,%2,%3}, [%4];" \
        : "=r"(R0), "=r"(R1), "=r"(R2), "=r"(R3) : "r"(ADDR))

__device__ __forceinline__ float safe_scale(float s, float m, float mn) {
    return (m > -1e37f) ? s * expf(m - mn) : 0.f;
}

__global__ void __launch_bounds__(256, 2) gemm_out_kernel(
    const float* __restrict__ W, const float* __restrict__ bias)
{
    __shared__ __nv_bfloat16 sA[2 * 128 * 32];   // 16KB (2 stages)
    __shared__ __nv_bfloat16 sB[2 * 32 * 128];   // 16KB (2 stages)
    __shared__ float2 spart[128][4];

    const int K = 1024;
    int tid = threadIdx.x;
    int warp = tid >> 5, lane = tid & 31, g = lane >> 2, q = lane & 3;
    int wm = warp & 1, wn = warp >> 1;
    int bm0 = blockIdx.x * 128, bn0 = blockIdx.y * 128;
    bool fullTile = (bn0 + 128 <= V_SZ);

    uint32_t sA_b = (uint32_t)__cvta_generic_to_shared(sA);
    uint32_t sB_b = (uint32_t)__cvta_generic_to_shared(sB);

    // loader lane geometry
    int a_r = tid >> 2, a_c = tid & 3;           // A: 128 rows x 4 chunks, x2 halves
    int b_kr = tid >> 4, b_c = tid & 15;         // B: 32 rows x 16 chunks, x2 halves
    uint32_t a_sts0 = a_r * 64 + ((a_c ^ ((a_r >> 1) & 3)) << 4);
    uint32_t a_sts1 = (a_r + 64) * 64 + ((a_c ^ (((a_r + 64) >> 1) & 3)) << 4);
    uint32_t b_sts0 = b_kr * 256 + ((b_c ^ (b_kr & 7)) << 4);
    uint32_t b_sts1 = (b_kr + 16) * 256 + ((b_c ^ ((b_kr + 16) & 7)) << 4);

    // fragment ldmatrix geometry
    int a_row[4];
    #pragma unroll
    for (int mt = 0; mt < 4; mt++) a_row[mt] = wm * 64 + mt * 16 + (lane & 15);
    int b_lk = lane & 15, b_lc = lane >> 4;

    float acc[4][4][4];
    #pragma unroll
    for (int i = 0; i < 4; i++)
        #pragma unroll
        for (int j = 0; j < 4; j++)
            #pragma unroll
            for (int t = 0; t < 4; t++) acc[i][j][t] = 0.f;

    // ---- prologue: stage 0 ----
    {
        uint4 va0 = *(const uint4*)(g_h1b + (size_t)(bm0 + a_r) * K + a_c * 8);
        uint4 va1 = *(const uint4*)(g_h1b + (size_t)(bm0 + a_r + 64) * K + a_c * 8);
        *(uint4*)((char*)sA + a_sts0) = va0;
        *(uint4*)((char*)sA + a_sts1) = va1;
        #pragma unroll
        for (int s = 0; s < 2; s++) {
            int kr = b_kr + s * 16;
            const float* wp = W + (size_t)kr * V_SZ + bn0 + b_c * 8;
            float f[8];
            if (fullTile) {
                #pragma unroll
                for (int j = 0; j < 8; j++) f[j] = wp[j];
            } else {
                #pragma unroll
                for (int j = 0; j < 8; j++)
                    f[j] = (bn0 + b_c * 8 + j < V_SZ) ? wp[j] : 0.f;
            }
            __nv_bfloat162 p0 = __floats2bfloat162_rn(f[0], f[1]);
            __nv_bfloat162 p1 = __floats2bfloat162_rn(f[2], f[3]);
            __nv_bfloat162 p2 = __floats2bfloat162_rn(f[4], f[5]);
            __nv_bfloat162 p3 = __floats2bfloat162_rn(f[6], f[7]);
            uint4 v; v.x = *(unsigned*)&p0; v.y = *(unsigned*)&p1;
            v.z = *(unsigned*)&p2; v.w = *(unsigned*)&p3;
            *(uint4*)((char*)sB + (s == 0 ? b_sts0 : b_sts1)) = v;
        }
    }
    __syncthreads();

    // ---- main loop ----
    for (int ks = 0; ks < 32; ks++) {
        int buf = ks & 1;
        bool hasNext = ks < 31;
        uint4 va0, va1, vb0, vb1;

        if (hasNext) {
            int k0 = (ks + 1) * 32;
            va0 = *(const uint4*)(g_h1b + (size_t)(bm0 + a_r) * K + k0 + a_c * 8);
            va1 = *(const uint4*)(g_h1b + (size_t)(bm0 + a_r + 64) * K + k0 + a_c * 8);
            #pragma unroll
            for (int s = 0; s < 2; s++) {
                int kr = b_kr + s * 16;
                const float* wp = W + (size_t)(k0 + kr) * V_SZ + bn0 + b_c * 8;
                float f[8];
                if (fullTile) {
                    #pragma unroll
                    for (int j = 0; j < 8; j++) f[j] = wp[j];
                } else {
                    #pragma unroll
                    for (int j = 0; j < 8; j++)
                        f[j] = (bn0 + b_c * 8 + j < V_SZ) ? wp[j] : 0.f;
                }
                __nv_bfloat162 p0 = __floats2bfloat162_rn(f[0], f[1]);
                __nv_bfloat162 p1 = __floats2bfloat162_rn(f[2], f[3]);
                __nv_bfloat162 p2 = __floats2bfloat162_rn(f[4], f[5]);
                __nv_bfloat162 p3 = __floats2bfloat162_rn(f[6], f[7]);
                uint4 v; v.x = *(unsigned*)&p0; v.y = *(unsigned*)&p1;
                v.z = *(unsigned*)&p2; v.w = *(unsigned*)&p3;
                if (s == 0) vb0 = v; else vb1 = v;
            }
        }

        uint32_t ab = sA_b + buf * (128 * 32 * 2);
        uint32_t bb = sB_b + buf * (32 * 128 * 2);
        #pragma unroll
        for (int kk = 0; kk < 2; kk++) {
            unsigned a[4][4], b[4][2];
            #pragma unroll
            for (int mt = 0; mt < 4; mt++) {
                int chunk = kk * 2 + (lane >> 4);
                uint32_t addr = ab + a_row[mt] * 64 +
                                ((chunk ^ ((a_row[mt] >> 1) & 3)) << 4);
                LDMX4(a[mt][0], a[mt][1], a[mt][2], a[mt][3], addr);
            }
            #pragma unroll
            for (int h = 0; h < 2; h++) {
                int krow = kk * 16 + b_lk;
                int c = wn * 4 + 2 * h + b_lc;
                uint32_t addr = bb + krow * 256 + ((c ^ (krow & 7)) << 4);
                unsigned r0, r1, r2, r3;
                LDMX4T(r0, r1, r2, r3, addr);
                b[2 * h][0] = r0;     b[2 * h][1] = r1;
                b[2 * h + 1][0] = r2; b[2 * h + 1][1] = r3;
            }
            #pragma unroll
            for (int mt = 0; mt < 4; mt++)
                #pragma unroll
                for (int nt = 0; nt < 4; nt++)
                    asm volatile(
                        "mma.sync.aligned.m16n8k16.row.col.f32.bf16.bf16.f32 "
                        "{%0,%1,%2,%3}, {%4,%5,%6,%7}, {%8,%9}, {%0,%1,%2,%3};"
                        : "+f"(acc[mt][nt][0]), "+f"(acc[mt][nt][1]),
                          "+f"(acc[mt][nt][2]), "+f"(acc[mt][nt][3])
                        : "r"(a[mt][0]), "r"(a[mt][1]), "r"(a[mt][2]), "r"(a[mt][3]),
                          "r"(b[nt][0]), "r"(b[nt][1]));
        }

        if (hasNext) {
            uint32_t ao = (buf ^ 1) * (128 * 32 * 2);
            uint32_t bo = (buf ^ 1) * (32 * 128 * 2);
            *(uint4*)((char*)sA + ao + a_sts0) = va0;
            *(uint4*)((char*)sA + ao + a_sts1) = va1;
            *(uint4*)((char*)sB + bo + b_sts0) = vb0;
            *(uint4*)((char*)sB + bo + b_sts1) = vb1;
        }
        __syncthreads();
    }

    // ---- epilogue: bias, store logits, per-row (max,sumexp) partials ----
    #pragma unroll
    for (int mt = 0; mt < 4; mt++) {
        int row = bm0 + wm * 64 + mt * 16 + g;
        #pragma unroll
        for (int nt = 0; nt < 4; nt++) {
            int col = bn0 + wn * 32 + nt * 8 + 2 * q;
            float b0 = (col < V_SZ)     ? bias[col]     : 0.f;
            float b1 = (col + 1 < V_SZ) ? bias[col + 1] : 0.f;
            acc[mt][nt][0] = (col < V_SZ)     ? acc[mt][nt][0] + b0 : -1e38f;
            acc[mt][nt][1] = (col + 1 < V_SZ) ? acc[mt][nt][1] + b1 : -1e38f;
            acc[mt][nt][2] = (col < V_SZ)     ? acc[mt][nt][2] + b0 : -1e38f;
            acc[mt][nt][3] = (col + 1 < V_SZ) ? acc[mt][nt][3] + b1 : -1e38f;
            float* p0 = g_logits + (size_t)row * LDL + col;
            float* p1 = g_logits + (size_t)(row + 8) * LDL + col;
            p0[0] = acc[mt][nt][0]; p0[1] = acc[mt][nt][1];
            p1[0] = acc[mt][nt][2]; p1[1] = acc[mt][nt][3];
        }
    }

    #pragma unroll
    for (int mt = 0; mt < 4; mt++) {
        #pragma unroll
        for (int half = 0; half < 2; half++) {
            int lr = wm * 64 + mt * 16 + g + 8 * half;
            float mx = -1e38f, sm = 0.f;
            #pragma unroll
            for (int nt = 0; nt < 4; nt++)
                mx = fmaxf(mx, fmaxf(acc[mt][nt][2 * half], acc[mt][nt][2 * half + 1]));
            #pragma unroll
            for (int nt = 0; nt < 4; nt++) {
                float v0 = acc[mt][nt][2 * half], v1 = acc[mt][nt][2 * half + 1];
                if (v0 > -1e37f) sm += expf(v0 - mx);
                if (v1 > -1e37f) sm += expf(v1 - mx);
            }
            #pragma unroll
            for (int o = 1; o <= 2; o <<= 1) {
                float mo = __shfl_xor_sync(0xffffffffu, mx, o);
                float so = __shfl_xor_sync(0xffffffffu, sm, o);
                float mn = fmaxf(mx, mo);
                sm = safe_scale(sm, mx, mn) + safe_scale(so, mo, mn);
                mx = mn;
            }
            if (q == 0) spart[lr][wn] = make_float2(mx, sm);
        }
    }
    __syncthreads();
    if (tid < 128) {
        float mx = -1e38f, sm = 0.f;
        #pragma unroll
        for (int w = 0; w < 4; w++) {
            float2 p = spart[tid][w];
            float mn = fmaxf(mx, p.x);
            sm = safe_scale(sm, mx, mn) + safe_scale(p.y, p.x, mn);
            mx = mn;
        }
        g_part[(size_t)(bm0 + tid) * 400 + blockIdx.y] = make_float2(mx, sm);
    }
}

// ===========================================================================
// K6: log_softmax from partials: reduce 393 (max,sum), then one pass.
// ===========================================================================
__global__ void __launch_bounds__(256) lsm_kernel(float* __restrict__ outp)
{
    __shared__ float sredm[8];
    __shared__ float sreds[8];
    int row = blockIdx.x, tid = threadIdx.x, lane = tid & 31, warp = tid >> 5;

    float m = -1e38f, s = 0.f;
    for (int i = tid; i < NB_T; i += 256) {
        float2 p = g_part[(size_t)row * 400 + i];
        float mn = fmaxf(m, p.x);
        s = safe_scale(s, m, mn) + safe_scale(p.y, p.x, mn);
        m = mn;
    }
    #pragma unroll
    for (int o = 16; o; o >>= 1) {
        float mo = __shfl_xor_sync(0xffffffffu, m, o);
        float so = __shfl_xor_sync(0xffffffffu, s, o);
        float mn = fmaxf(m, mo);
        s = safe_scale(s, m, mn) + safe_scale(so, mo, mn);
        m = mn;
    }
    if (lane == 0) { sredm[warp] = m; sreds[warp] = s; }
    __syncthreads();
    float mall = sredm[0];
    #pragma unroll
    for (int i = 1; i < 8; i++) mall = fmaxf(mall, sredm[i]);
    float tot = 0.f;
    #pragma unroll
    for (int i = 0; i < 8; i++) tot += safe_scale(sreds[i], sredm[i], mall);
    float lse = mall + logf(tot);

    const float* lg = g_logits + (size_t)row * LDL;
    float* op = outp + (size_t)row * V_SZ;
    for (int v = tid * 4; v + 3 < V_SZ; v += 1024) {
        float4 x = *(const float4*)(lg + v);
        op[v]     = x.x - lse;
        op[v + 1] = x.y - lse;
        op[v + 2] = x.z - lse;
        op[v + 3] = x.w - lse;
    }
    if (tid == 0) op[V_SZ - 1] = lg[V_SZ - 1] - lse;   // 50256 tail
}

// ===========================================================================
// host launcher — kernel launches only
// ===========================================================================
extern "C" void kernel_launch(void* const* d_in, const int* in_sizes, int n_in,
                              void* d_out, int out_size)
{
    const float* input_emb = (const float*)d_in[0];
    const float* hidden    = (const float*)d_in[1];
    const float* enc       = (const float*)d_in[2];
    const float* attn_W    = (const float*)d_in[3];
    const float* attn_b    = (const float*)d_in[4];
    const float* comb_W    = (const float*)d_in[5];
    const float* comb_b    = (const float*)d_in[6];
    const float* W_ih      = (const float*)d_in[7];
    const float* W_hh      = (const float*)d_in[8];
    const float* b_ih      = (const float*)d_in[9];
    const float* b_hh      = (const float*)d_in[10];
    const float* out_W     = (const float*)d_in[11];
    const float* out_b     = (const float*)d_in[12];

    float* outp = (float*)d_out;
    long long osz = (long long)out_size;
    const long long OV = (long long)B_SZ * V_SZ;
    float* h1_out = (osz >= OV + (long long)B_SZ * H_SZ)
                        ? outp + (size_t)OV : nullptr;
    float* aw_out = (osz >= OV + (long long)B_SZ * H_SZ + (long long)B_SZ * L_SZ)
                        ? outp + (size_t)OV + (size_t)B_SZ * H_SZ : nullptr;

    attn_kernel<<<B_SZ / 4, 256>>>(input_emb, hidden, enc, attn_W, attn_b, aw_out);

    {
        dim3 grid(B_SZ / 64, 16, 4);   // z=0: comb (8x16); z=1..3: ghh (8x48)
        gemm_comb_ghh_kernel<<<grid, 256>>>(comb_W, comb_b, hidden, W_hh, b_hh);
    }
    {
        dim3 grid(B_SZ / 64, 3 * H_SZ / 64);
        gemm_gih_kernel<<<grid, 256>>>(W_ih, b_ih);
    }
    gru_kernel<<<(B_SZ * H_SZ) / 256, 256>>>(hidden, h1_out);

    {
        dim3 grid(B_SZ / 128, NB_T);   // m fastest -> 4 blocks share W tile in L2
        gemm_out_kernel<<<grid, 256>>>(out_W, out_b);
    }
    lsm_kernel<<<B_SZ, 256>>>(outp);
}

// round 4
// speedup vs baseline: 1.3317x; 1.2350x over previous
#include <cuda_runtime.h>
#include <cuda_bf16.h>
#include <cstdint>

#define B_SZ 512
#define H_SZ 1024
#define L_SZ 64
#define V_SZ 50257
#define LDL  50304   // padded logits / W row stride (128*393, 16B-aligned rows)
#define NB_T 393     // 128-wide n-tiles in vocab GEMM

// ---------------- scratch (device globals; no allocation allowed) ----------
__device__ float g_xin[B_SZ * 2 * H_SZ];
__device__ float g_x[B_SZ * H_SZ];
__device__ float g_gi[B_SZ * 3 * H_SZ];
__device__ float g_gh[B_SZ * 3 * H_SZ];
__device__ __nv_bfloat16 g_h1b[B_SZ * H_SZ];
__device__ __nv_bfloat16 g_wbf[(size_t)H_SZ * LDL];   // bf16 out_W, padded, 103MB
__device__ float g_logits[(size_t)B_SZ * LDL];
__device__ float2 g_part[B_SZ * 400];

// ---------------- cp.async helpers ----------------
__device__ __forceinline__ void cp_async16_cg(uint32_t dst, const void* src) {
    asm volatile("cp.async.cg.shared.global [%0], [%1], 16;" :: "r"(dst), "l"(src));
}
__device__ __forceinline__ void cp_async16_ca(uint32_t dst, const void* src) {
    asm volatile("cp.async.ca.shared.global [%0], [%1], 16;" :: "r"(dst), "l"(src));
}
__device__ __forceinline__ void cp_commit() {
    asm volatile("cp.async.commit_group;");
}
template <int N>
__device__ __forceinline__ void cp_wait() {
    asm volatile("cp.async.wait_group %0;" :: "n"(N));
}

// ===========================================================================
// K0: convert out_W fp32 (1024 x 50257, rows 4B-aligned) -> bf16 padded
// ===========================================================================
__global__ void __launch_bounds__(256) convw_kernel(const float* __restrict__ W)
{
    size_t id = (size_t)blockIdx.x * 256 + threadIdx.x;   // over 1024 * 25152
    int k  = (int)(id / (LDL / 2));
    int n2 = (int)(id % (LDL / 2)) * 2;
    const float* wr = W + (size_t)k * V_SZ;
    float f0 = (n2     < V_SZ) ? wr[n2]     : 0.f;
    float f1 = (n2 + 1 < V_SZ) ? wr[n2 + 1] : 0.f;
    __nv_bfloat162 p = __floats2bfloat162_rn(f0, f1);
    *(unsigned*)(&g_wbf[(size_t)k * LDL + n2]) = *(unsigned*)&p;
}

// ===========================================================================
// K1: attention (scores -> softmax -> attn_applied) + build concat input
// ===========================================================================
__global__ void __launch_bounds__(256) attn_kernel(
    const float* __restrict__ emb, const float* __restrict__ h0,
    const float* __restrict__ enc, const float* __restrict__ attn_W,
    const float* __restrict__ attn_b, float* __restrict__ aw_out)
{
    __shared__ float sE[4][H_SZ];
    __shared__ float sH[4][H_SZ];
    __shared__ float sS[4][L_SZ];
    __shared__ float sP[4][4][L_SZ];

    int tid = threadIdx.x;
    int r0  = blockIdx.x * 4;

    for (int i = tid; i < 4 * H_SZ; i += 256) {
        int r = i >> 10, c = i & 1023;
        sE[r][c] = emb[(size_t)(r0 + r) * H_SZ + c];
        sH[r][c] = h0 [(size_t)(r0 + r) * H_SZ + c];
    }
    __syncthreads();

    {
        int l = tid & 63, gq = tid >> 6;
        float acc[4] = {0.f, 0.f, 0.f, 0.f};
        int kbeg = gq * 512, kend = kbeg + 512;
        for (int k = kbeg; k < kend; k++) {
            float w = attn_W[(size_t)k * L_SZ + l];
            if (k < H_SZ) {
                #pragma unroll
                for (int r = 0; r < 4; r++) acc[r] += sE[r][k] * w;
            } else {
                #pragma unroll
                for (int r = 0; r < 4; r++) acc[r] += sH[r][k - H_SZ] * w;
            }
        }
        #pragma unroll
        for (int r = 0; r < 4; r++) sP[gq][r][l] = acc[r];
    }
    __syncthreads();
    {
        int r = tid >> 6, l = tid & 63;
        sS[r][l] = sP[0][r][l] + sP[1][r][l] + sP[2][r][l] + sP[3][r][l] + attn_b[l];
    }
    __syncthreads();

    int warp = tid >> 5, lane = tid & 31;
    if (warp < 4) {
        int r = warp;
        float v0 = sS[r][lane], v1 = sS[r][lane + 32];
        float m = fmaxf(v0, v1);
        #pragma unroll
        for (int o = 16; o; o >>= 1) m = fmaxf(m, __shfl_xor_sync(0xffffffffu, m, o));
        float e0 = expf(v0 - m), e1 = expf(v1 - m);
        float s = e0 + e1;
        #pragma unroll
        for (int o = 16; o; o >>= 1) s += __shfl_xor_sync(0xffffffffu, s, o);
        float inv = 1.0f / s;
        float w0 = e0 * inv, w1 = e1 * inv;
        sS[r][lane] = w0; sS[r][lane + 32] = w1;
        if (aw_out) {
            aw_out[(size_t)(r0 + r) * L_SZ + lane]      = w0;
            aw_out[(size_t)(r0 + r) * L_SZ + lane + 32] = w1;
        }
    }
    __syncthreads();

    for (int cc = 0; cc < 4; cc++) {
        int h = cc * 256 + tid;
        float a[4] = {0.f, 0.f, 0.f, 0.f};
        for (int l = 0; l < L_SZ; l++) {
            float e = enc[(size_t)l * H_SZ + h];
            #pragma unroll
            for (int r = 0; r < 4; r++) a[r] += sS[r][l] * e;
        }
        #pragma unroll
        for (int r = 0; r < 4; r++) {
            g_xin[(size_t)(r0 + r) * (2 * H_SZ) + h]        = sE[r][h];
            g_xin[(size_t)(r0 + r) * (2 * H_SZ) + H_SZ + h] = a[r];
        }
    }
}

// ===========================================================================
// tf32 mma GEMM core: kstep 16, 2-stage cp.async double buffer.
//   b_kmajor=1: B stored (N,K) -> cp.async direct; =0: (K,N) -> reg transpose.
// ===========================================================================
__device__ __forceinline__ void gemm_tf32_core(
    float (*sA)[64][20], float (*sB)[64][20],
    const float* __restrict__ A, const float* __restrict__ Bm,
    const float* __restrict__ bias, float* __restrict__ C,
    int N, int K, int b_kmajor, int relu, int bm0, int bn0)
{
    int tid = threadIdx.x;
    int warp = tid >> 5, lane = tid & 31, g = lane >> 2, q = lane & 3;
    int wm = warp & 1, wn = warp >> 1;

    // loader geometry (kstep 16): 64 rows x 4 float4-chunks, 1 per thread
    int lr = tid >> 2, lc4 = (tid & 3) * 4;
    // !kmajor B loader: 16 k-rows x 16 float4 n-chunks
    int tkr = tid >> 4, tc4 = (tid & 15) * 4;

    float acc[2][2][4];
    #pragma unroll
    for (int i = 0; i < 2; i++)
        #pragma unroll
        for (int j = 0; j < 2; j++)
            #pragma unroll
            for (int t = 0; t < 4; t++) acc[i][j][t] = 0.f;

    const int NS = K / 16;

    // prologue: stage 0
    {
        cp_async16_ca((uint32_t)__cvta_generic_to_shared(&sA[0][lr][lc4]),
                      A + (size_t)(bm0 + lr) * K + lc4);
        if (b_kmajor) {
            cp_async16_cg((uint32_t)__cvta_generic_to_shared(&sB[0][lr][lc4]),
                          Bm + (size_t)(bn0 + lr) * K + lc4);
        } else {
            float4 v = *(const float4*)(Bm + (size_t)tkr * N + bn0 + tc4);
            sB[0][tc4][tkr] = v.x; sB[0][tc4 + 1][tkr] = v.y;
            sB[0][tc4 + 2][tkr] = v.z; sB[0][tc4 + 3][tkr] = v.w;
        }
        cp_commit();
    }

    for (int ks = 0; ks < NS; ks++) {
        int buf = ks & 1;
        bool hasNext = (ks + 1) < NS;
        cp_wait<0>();
        __syncthreads();
        float4 vB;
        if (hasNext) {
            int k0 = (ks + 1) * 16;
            int nb = buf ^ 1;
            cp_async16_ca((uint32_t)__cvta_generic_to_shared(&sA[nb][lr][lc4]),
                          A + (size_t)(bm0 + lr) * K + k0 + lc4);
            if (b_kmajor)
                cp_async16_cg((uint32_t)__cvta_generic_to_shared(&sB[nb][lr][lc4]),
                              Bm + (size_t)(bn0 + lr) * K + k0 + lc4);
            else
                vB = *(const float4*)(Bm + (size_t)(k0 + tkr) * N + bn0 + tc4);
            cp_commit();
        }

        #pragma unroll
        for (int kk = 0; kk < 2; kk++) {
            int ko = kk * 8;
            unsigned a[2][4], b[2][2];
            #pragma unroll
            for (int mt = 0; mt < 2; mt++) {
                int rm = wm * 32 + mt * 16;
                a[mt][0] = __float_as_uint(sA[buf][rm + g][ko + q]);
                a[mt][1] = __float_as_uint(sA[buf][rm + g + 8][ko + q]);
                a[mt][2] = __float_as_uint(sA[buf][rm + g][ko + q + 4]);
                a[mt][3] = __float_as_uint(sA[buf][rm + g + 8][ko + q + 4]);
            }
            #pragma unroll
            for (int nt = 0; nt < 2; nt++) {
                int cn = wn * 16 + nt * 8 + g;
                b[nt][0] = __float_as_uint(sB[buf][cn][ko + q]);
                b[nt][1] = __float_as_uint(sB[buf][cn][ko + q + 4]);
            }
            #pragma unroll
            for (int mt = 0; mt < 2; mt++)
                #pragma unroll
                for (int nt = 0; nt < 2; nt++)
                    asm volatile(
                        "mma.sync.aligned.m16n8k8.row.col.f32.tf32.tf32.f32 "
                        "{%0,%1,%2,%3}, {%4,%5,%6,%7}, {%8,%9}, {%0,%1,%2,%3};"
                        : "+f"(acc[mt][nt][0]), "+f"(acc[mt][nt][1]),
                          "+f"(acc[mt][nt][2]), "+f"(acc[mt][nt][3])
                        : "r"(a[mt][0]), "r"(a[mt][1]), "r"(a[mt][2]), "r"(a[mt][3]),
                          "r"(b[nt][0]), "r"(b[nt][1]));
        }

        if (hasNext && !b_kmajor) {
            int nb = buf ^ 1;
            sB[nb][tc4][tkr] = vB.x; sB[nb][tc4 + 1][tkr] = vB.y;
            sB[nb][tc4 + 2][tkr] = vB.z; sB[nb][tc4 + 3][tkr] = vB.w;
        }
    }

    #pragma unroll
    for (int mt = 0; mt < 2; mt++) {
        int row = bm0 + wm * 32 + mt * 16 + g;
        #pragma unroll
        for (int nt = 0; nt < 2; nt++) {
            int col = bn0 + wn * 16 + nt * 8 + 2 * q;
            float b0 = bias[col], b1 = bias[col + 1];
            float v0 = acc[mt][nt][0] + b0, v1 = acc[mt][nt][1] + b1;
            float v2 = acc[mt][nt][2] + b0, v3 = acc[mt][nt][3] + b1;
            if (relu) {
                v0 = fmaxf(v0, 0.f); v1 = fmaxf(v1, 0.f);
                v2 = fmaxf(v2, 0.f); v3 = fmaxf(v3, 0.f);
            }
            C[(size_t)row * N + col] = v0;       C[(size_t)row * N + col + 1] = v1;
            C[(size_t)(row + 8) * N + col] = v2; C[(size_t)(row + 8) * N + col + 1] = v3;
        }
    }
}

__global__ void __launch_bounds__(256) gemm_comb_ghh_kernel(
    const float* __restrict__ comb_W, const float* __restrict__ comb_b,
    const float* __restrict__ h0, const float* __restrict__ W_hh,
    const float* __restrict__ b_hh)
{
    __shared__ float sA[2][64][20];
    __shared__ float sB[2][64][20];
    if (blockIdx.z == 0) {
        gemm_tf32_core(sA, sB, g_xin, comb_W, comb_b, g_x,
                       H_SZ, 2 * H_SZ, 0, 1, blockIdx.x * 64, blockIdx.y * 64);
    } else {
        int bn = (blockIdx.z - 1) * 16 + blockIdx.y;
        gemm_tf32_core(sA, sB, h0, W_hh, b_hh, g_gh,
                       3 * H_SZ, H_SZ, 1, 0, blockIdx.x * 64, bn * 64);
    }
}
__global__ void __launch_bounds__(256) gemm_gih_kernel(
    const float* __restrict__ W_ih, const float* __restrict__ b_ih)
{
    __shared__ float sA[2][64][20];
    __shared__ float sB[2][64][20];
    gemm_tf32_core(sA, sB, g_x, W_ih, b_ih, g_gi,
                   3 * H_SZ, H_SZ, 1, 0, blockIdx.x * 64, blockIdx.y * 64);
}

// ===========================================================================
// K4: GRU elementwise
// ===========================================================================
__global__ void __launch_bounds__(256) gru_kernel(
    const float* __restrict__ h0, float* __restrict__ h1_extra)
{
    int idx = blockIdx.x * 256 + threadIdx.x;
    if (idx >= B_SZ * H_SZ) return;
    int row = idx >> 10, j = idx & 1023;
    const float* gi = g_gi + (size_t)row * 3 * H_SZ;
    const float* gh = g_gh + (size_t)row * 3 * H_SZ;
    float rg = 1.f / (1.f + expf(-(gi[j] + gh[j])));
    float zg = 1.f / (1.f + expf(-(gi[H_SZ + j] + gh[H_SZ + j])));
    float ng = tanhf(gi[2 * H_SZ + j] + rg * gh[2 * H_SZ + j]);
    float h0v = h0[idx];
    float h1 = (1.f - zg) * ng + zg * h0v;
    g_h1b[idx] = __float2bfloat16(h1);
    if (h1_extra) h1_extra[idx] = h1;
}

// ===========================================================================
// K5: vocab GEMM, pure bf16 cp.async 5-stage pipeline + ldmatrix.
//   logits = h1b(512x1024) @ g_wbf(1024xLDL) + out_b
//   Tile 128m x 128n x 32k, 8 warps (2m x 4n), m16n8k16.
//   A smem (m,k): 64B rows, chunk swizzle c ^ ((r>>1)&3)
//   B smem (k,n): 256B rows, chunk swizzle c ^ (k&7)
//   dynamic smem: 5 stages x (8KB A + 8KB B) = 80KB
// ===========================================================================
#define LDMX4(R0,R1,R2,R3,ADDR) \
    asm volatile("ldmatrix.sync.aligned.m8n8.x4.shared.b16 {%0,%1,%2,%3}, [%4];" \
        : "=r"(R0), "=r"(R1), "=r"(R2), "=r"(R3) : "r"(ADDR))
#define LDMX4T(R0,R1,R2,R3,ADDR) \
    asm volatile("ldmatrix.sync.aligned.m8n8.x4.trans.shared.b16 {%0,%1,%2,%3}, [%4];" \
        : "=r"(R0), "=r"(R1), "=r"(R2), "=r"(R3) : "r"(ADDR))

__device__ __forceinline__ float safe_scale(float s, float m, float mn) {
    return (m > -1e37f) ? s * expf(m - mn) : 0.f;
}

#define OUT_STAGES 5
#define A_STAGE_B  8192
#define B_STAGE_B  8192

__global__ void __launch_bounds__(256, 2) gemm_out_kernel(
    const float* __restrict__ bias)
{
    extern __shared__ __nv_bfloat16 dynsmem[];
    __shared__ float2 spart[128][4];

    const int K = 1024;
    int tid = threadIdx.x;
    int warp = tid >> 5, lane = tid & 31, g = lane >> 2, q = lane & 3;
    int wm = warp & 1, wn = warp >> 1;
    int bm0 = blockIdx.x * 128, bn0 = blockIdx.y * 128;

    uint32_t smem_b = (uint32_t)__cvta_generic_to_shared(dynsmem);
    uint32_t sB_b   = smem_b + OUT_STAGES * A_STAGE_B;

    // loader geometry: 2 x 16B chunks each for A and B per thread per stage
    int a_r0 = tid >> 2,  a_c0 = tid & 3;          // + 64 rows for second chunk
    int b_k0 = tid >> 4,  b_c0 = tid & 15;         // + 16 rows for second chunk
    uint32_t a_dst0 = a_r0 * 64 + ((a_c0 ^ ((a_r0 >> 1) & 3)) << 4);
    uint32_t a_dst1 = (a_r0 + 64) * 64 + ((a_c0 ^ (((a_r0 + 64) >> 1) & 3)) << 4);
    uint32_t b_dst0 = b_k0 * 256 + ((b_c0 ^ (b_k0 & 7)) << 4);
    uint32_t b_dst1 = (b_k0 + 16) * 256 + ((b_c0 ^ ((b_k0 + 16) & 7)) << 4);
    const __nv_bfloat16* a_src0 = g_h1b + (size_t)(bm0 + a_r0) * K + a_c0 * 8;
    const __nv_bfloat16* a_src1 = g_h1b + (size_t)(bm0 + a_r0 + 64) * K + a_c0 * 8;
    const __nv_bfloat16* b_src0 = g_wbf + (size_t)b_k0 * LDL + bn0 + b_c0 * 8;
    const __nv_bfloat16* b_src1 = g_wbf + (size_t)(b_k0 + 16) * LDL + bn0 + b_c0 * 8;

    // fragment geometry
    int a_row[4];
    #pragma unroll
    for (int mt = 0; mt < 4; mt++) a_row[mt] = wm * 64 + mt * 16 + (lane & 15);
    int b_lk = lane & 15, b_lc = lane >> 4;

    float acc[4][4][4];
    #pragma unroll
    for (int i = 0; i < 4; i++)
        #pragma unroll
        for (int j = 0; j < 4; j++)
            #pragma unroll
            for (int t = 0; t < 4; t++) acc[i][j][t] = 0.f;

    // prologue: stages 0..3
    #pragma unroll
    for (int st = 0; st < OUT_STAGES - 1; st++) {
        uint32_t ab = smem_b + st * A_STAGE_B;
        uint32_t bb = sB_b   + st * B_STAGE_B;
        int k0 = st * 32;
        cp_async16_ca(ab + a_dst0, a_src0 + k0);
        cp_async16_ca(ab + a_dst1, a_src1 + k0);
        cp_async16_cg(bb + b_dst0, b_src0 + (size_t)k0 * LDL);
        cp_async16_cg(bb + b_dst1, b_src1 + (size_t)k0 * LDL);
        cp_commit();
    }

    int slot = 0;
    for (int ks = 0; ks < 32; ks++) {
        cp_wait<OUT_STAGES - 2>();
        __syncthreads();

        uint32_t ab = smem_b + slot * A_STAGE_B;
        uint32_t bb = sB_b   + slot * B_STAGE_B;
        #pragma unroll
        for (int kk = 0; kk < 2; kk++) {
            unsigned a[4][4], b[4][2];
            #pragma unroll
            for (int mt = 0; mt < 4; mt++) {
                int chunk = kk * 2 + (lane >> 4);
                uint32_t addr = ab + a_row[mt] * 64 +
                                ((chunk ^ ((a_row[mt] >> 1) & 3)) << 4);
                LDMX4(a[mt][0], a[mt][1], a[mt][2], a[mt][3], addr);
            }
            #pragma unroll
            for (int h = 0; h < 2; h++) {
                int krow = kk * 16 + b_lk;
                int c = wn * 4 + 2 * h + b_lc;
                uint32_t addr = bb + krow * 256 + ((c ^ (krow & 7)) << 4);
                unsigned r0, r1, r2, r3;
                LDMX4T(r0, r1, r2, r3, addr);
                b[2 * h][0] = r0;     b[2 * h][1] = r1;
                b[2 * h + 1][0] = r2; b[2 * h + 1][1] = r3;
            }
            #pragma unroll
            for (int mt = 0; mt < 4; mt++)
                #pragma unroll
                for (int nt = 0; nt < 4; nt++)
                    asm volatile(
                        "mma.sync.aligned.m16n8k16.row.col.f32.bf16.bf16.f32 "
                        "{%0,%1,%2,%3}, {%4,%5,%6,%7}, {%8,%9}, {%0,%1,%2,%3};"
                        : "+f"(acc[mt][nt][0]), "+f"(acc[mt][nt][1]),
                          "+f"(acc[mt][nt][2]), "+f"(acc[mt][nt][3])
                        : "r"(a[mt][0]), "r"(a[mt][1]), "r"(a[mt][2]), "r"(a[mt][3]),
                          "r"(b[nt][0]), "r"(b[nt][1]));
        }

        int nst = ks + OUT_STAGES - 1;
        if (nst < 32) {
            int wslot = nst % OUT_STAGES;
            uint32_t ab2 = smem_b + wslot * A_STAGE_B;
            uint32_t bb2 = sB_b   + wslot * B_STAGE_B;
            int k0 = nst * 32;
            cp_async16_ca(ab2 + a_dst0, a_src0 + k0);
            cp_async16_ca(ab2 + a_dst1, a_src1 + k0);
            cp_async16_cg(bb2 + b_dst0, b_src0 + (size_t)k0 * LDL);
            cp_async16_cg(bb2 + b_dst1, b_src1 + (size_t)k0 * LDL);
            cp_commit();
        }
        slot = (slot + 1 == OUT_STAGES) ? 0 : slot + 1;
    }

    // ---- epilogue: bias, store logits, per-row (max,sumexp) partials ----
    #pragma unroll
    for (int mt = 0; mt < 4; mt++) {
        int row = bm0 + wm * 64 + mt * 16 + g;
        #pragma unroll
        for (int nt = 0; nt < 4; nt++) {
            int col = bn0 + wn * 32 + nt * 8 + 2 * q;
            float b0 = (col < V_SZ)     ? bias[col]     : 0.f;
            float b1 = (col + 1 < V_SZ) ? bias[col + 1] : 0.f;
            acc[mt][nt][0] = (col < V_SZ)     ? acc[mt][nt][0] + b0 : -1e38f;
            acc[mt][nt][1] = (col + 1 < V_SZ) ? acc[mt][nt][1] + b1 : -1e38f;
            acc[mt][nt][2] = (col < V_SZ)     ? acc[mt][nt][2] + b0 : -1e38f;
            acc[mt][nt][3] = (col + 1 < V_SZ) ? acc[mt][nt][3] + b1 : -1e38f;
            float* p0 = g_logits + (size_t)row * LDL + col;
            float* p1 = g_logits + (size_t)(row + 8) * LDL + col;
            p0[0] = acc[mt][nt][0]; p0[1] = acc[mt][nt][1];
            p1[0] = acc[mt][nt][2]; p1[1] = acc[mt][nt][3];
        }
    }

    #pragma unroll
    for (int mt = 0; mt < 4; mt++) {
        #pragma unroll
        for (int half = 0; half < 2; half++) {
            int lr = wm * 64 + mt * 16 + g + 8 * half;
            float mx = -1e38f, sm = 0.f;
            #pragma unroll
            for (int nt = 0; nt < 4; nt++)
                mx = fmaxf(mx, fmaxf(acc[mt][nt][2 * half], acc[mt][nt][2 * half + 1]));
            #pragma unroll
            for (int nt = 0; nt < 4; nt++) {
                float v0 = acc[mt][nt][2 * half], v1 = acc[mt][nt][2 * half + 1];
                if (v0 > -1e37f) sm += expf(v0 - mx);
                if (v1 > -1e37f) sm += expf(v1 - mx);
            }
            #pragma unroll
            for (int o = 1; o <= 2; o <<= 1) {
                float mo = __shfl_xor_sync(0xffffffffu, mx, o);
                float so = __shfl_xor_sync(0xffffffffu, sm, o);
                float mn = fmaxf(mx, mo);
                sm = safe_scale(sm, mx, mn) + safe_scale(so, mo, mn);
                mx = mn;
            }
            if (q == 0) spart[lr][wn] = make_float2(mx, sm);
        }
    }
    __syncthreads();
    if (tid < 128) {
        float mx = -1e38f, sm = 0.f;
        #pragma unroll
        for (int w = 0; w < 4; w++) {
            float2 p = spart[tid][w];
            float mn = fmaxf(mx, p.x);
            sm = safe_scale(sm, mx, mn) + safe_scale(p.y, p.x, mn);
            mx = mn;
        }
        g_part[(size_t)(bm0 + tid) * 400 + blockIdx.y] = make_float2(mx, sm);
    }
}

// ===========================================================================
// K6: log_softmax from partials
// ===========================================================================
__global__ void __launch_bounds__(256) lsm_kernel(float* __restrict__ outp)
{
    __shared__ float sredm[8];
    __shared__ float sreds[8];
    int row = blockIdx.x, tid = threadIdx.x, lane = tid & 31, warp = tid >> 5;

    float m = -1e38f, s = 0.f;
    for (int i = tid; i < NB_T; i += 256) {
        float2 p = g_part[(size_t)row * 400 + i];
        float mn = fmaxf(m, p.x);
        s = safe_scale(s, m, mn) + safe_scale(p.y, p.x, mn);
        m = mn;
    }
    #pragma unroll
    for (int o = 16; o; o >>= 1) {
        float mo = __shfl_xor_sync(0xffffffffu, m, o);
        float so = __shfl_xor_sync(0xffffffffu, s, o);
        float mn = fmaxf(m, mo);
        s = safe_scale(s, m, mn) + safe_scale(so, mo, mn);
        m = mn;
    }
    if (lane == 0) { sredm[warp] = m; sreds[warp] = s; }
    __syncthreads();
    float mall = sredm[0];
    #pragma unroll
    for (int i = 1; i < 8; i++) mall = fmaxf(mall, sredm[i]);
    float tot = 0.f;
    #pragma unroll
    for (int i = 0; i < 8; i++) tot += safe_scale(sreds[i], sredm[i], mall);
    float lse = mall + logf(tot);

    const float* lg = g_logits + (size_t)row * LDL;
    float* op = outp + (size_t)row * V_SZ;
    for (int v = tid * 4; v + 3 < V_SZ; v += 1024) {
        float4 x = *(const float4*)(lg + v);
        op[v]     = x.x - lse;
        op[v + 1] = x.y - lse;
        op[v + 2] = x.z - lse;
        op[v + 3] = x.w - lse;
    }
    if (tid == 0) op[V_SZ - 1] = lg[V_SZ - 1] - lse;
}

// ===========================================================================
// host launcher
// ===========================================================================
extern "C" void kernel_launch(void* const* d_in, const int* in_sizes, int n_in,
                              void* d_out, int out_size)
{
    const float* input_emb = (const float*)d_in[0];
    const float* hidden    = (const float*)d_in[1];
    const float* enc       = (const float*)d_in[2];
    const float* attn_W    = (const float*)d_in[3];
    const float* attn_b    = (const float*)d_in[4];
    const float* comb_W    = (const float*)d_in[5];
    const float* comb_b    = (const float*)d_in[6];
    const float* W_ih      = (const float*)d_in[7];
    const float* W_hh      = (const float*)d_in[8];
    const float* b_ih      = (const float*)d_in[9];
    const float* b_hh      = (const float*)d_in[10];
    const float* out_W     = (const float*)d_in[11];
    const float* out_b     = (const float*)d_in[12];

    float* outp = (float*)d_out;
    long long osz = (long long)out_size;
    const long long OV = (long long)B_SZ * V_SZ;
    float* h1_out = (osz >= OV + (long long)B_SZ * H_SZ)
                        ? outp + (size_t)OV : nullptr;
    float* aw_out = (osz >= OV + (long long)B_SZ * H_SZ + (long long)B_SZ * L_SZ)
                        ? outp + (size_t)OV + (size_t)B_SZ * H_SZ : nullptr;

    const int OUT_SMEM = OUT_STAGES * (A_STAGE_B + B_STAGE_B);   // 80KB
    cudaFuncSetAttribute(gemm_out_kernel,
                         cudaFuncAttributeMaxDynamicSharedMemorySize, OUT_SMEM);

    // K0: out_W fp32 -> bf16 padded (independent; first so DRAM streams early)
    convw_kernel<<<(H_SZ * (LDL / 2)) / 256, 256>>>(out_W);

    // K1: attention + concat
    attn_kernel<<<B_SZ / 4, 256>>>(input_emb, hidden, enc, attn_W, attn_b, aw_out);

    // K2+K3b fused
    {
        dim3 grid(B_SZ / 64, 16, 4);
        gemm_comb_ghh_kernel<<<grid, 256>>>(comb_W, comb_b, hidden, W_hh, b_hh);
    }
    // K3a
    {
        dim3 grid(B_SZ / 64, 3 * H_SZ / 64);
        gemm_gih_kernel<<<grid, 256>>>(W_ih, b_ih);
    }
    // K4
    gru_kernel<<<(B_SZ * H_SZ) / 256, 256>>>(hidden, h1_out);

    // K5
    {
        dim3 grid(B_SZ / 128, NB_T);
        gemm_out_kernel<<<grid, 256, OUT_SMEM>>>(out_b);
    }
    // K6
    lsm_kernel<<<B_SZ, 256>>>(outp);
}